// round 1
// baseline (speedup 1.0000x reference)
#include <cuda_runtime.h>

#define N_NODES 50000
#define N_EDGES 800000
#define F_IN    128
#define F_HID   64

// ---------------- scratch (no allocations allowed) ----------------
__device__ float g_deg_out[N_NODES];
__device__ float g_deg_in [N_NODES];
__device__ float g_norm_out[N_NODES];
__device__ float g_norm_in [N_NODES];
__device__ float g_h  [N_NODES * F_HID];   // transformed features (gemm output)
__device__ float g_t  [N_NODES * F_HID];   // post-layer1 activations (pre-scaled by norm_out)
__device__ float g_agg[N_NODES * F_HID];   // scatter-add accumulator

// ---------------- degree / norm ----------------
__global__ void zero_deg_kernel() {
    int i = blockIdx.x * blockDim.x + threadIdx.x;
    if (i < N_NODES) { g_deg_out[i] = 0.f; g_deg_in[i] = 0.f; }
}

__global__ void count_deg_kernel(const int* __restrict__ src, const int* __restrict__ dst) {
    int e = blockIdx.x * blockDim.x + threadIdx.x;
    if (e < N_EDGES) {
        atomicAdd(&g_deg_out[src[e]], 1.f);
        atomicAdd(&g_deg_in [dst[e]], 1.f);
    }
}

__global__ void norm_kernel() {
    int i = blockIdx.x * blockDim.x + threadIdx.x;
    if (i < N_NODES) {
        g_norm_out[i] = rsqrtf(fmaxf(g_deg_out[i], 1.f));
        g_norm_in [i] = rsqrtf(fmaxf(g_deg_in [i], 1.f));
    }
}

// ---------------- GEMM1: g_h = (x * norm_out) @ W1  (K=128, N=64) ----------------
// 32 rows per block, 256 threads; W1 resident in smem, 8 row-accumulators/thread.
__global__ void __launch_bounds__(256) gemm1_kernel(const float* __restrict__ x,
                                                    const float* __restrict__ W) {
    __shared__ float Ws[F_IN * F_HID];   // 32 KB
    __shared__ float xs[32 * F_IN];      // 16 KB
    int tid = threadIdx.x;
    for (int i = tid; i < F_IN * F_HID; i += 256) Ws[i] = W[i];
    int row0 = blockIdx.x * 32;
    for (int i = tid; i < 32 * F_IN; i += 256) {
        int r = i >> 7, k = i & 127;
        int row = row0 + r;
        xs[i] = (row < N_NODES) ? x[row * F_IN + k] * g_norm_out[row] : 0.f;
    }
    __syncthreads();
    int rr = tid >> 6;        // 0..3
    int f  = tid & 63;
    float acc[8];
#pragma unroll
    for (int i = 0; i < 8; i++) acc[i] = 0.f;
    for (int k = 0; k < F_IN; k++) {
        float w = Ws[k * F_HID + f];
#pragma unroll
        for (int i = 0; i < 8; i++) acc[i] += xs[(rr + 4 * i) * F_IN + k] * w;
    }
#pragma unroll
    for (int i = 0; i < 8; i++) {
        int row = row0 + rr + 4 * i;
        if (row < N_NODES) g_h[row * F_HID + f] = acc[i];
    }
}

// ---------------- GEMM2: g_h = g_t @ W2  (K=64, N=64) ----------------
__global__ void __launch_bounds__(256) gemm2_kernel(const float* __restrict__ W) {
    __shared__ float Ws[F_HID * F_HID];  // 16 KB
    __shared__ float xs[32 * F_HID];     // 8 KB
    int tid = threadIdx.x;
    for (int i = tid; i < F_HID * F_HID; i += 256) Ws[i] = W[i];
    int row0 = blockIdx.x * 32;
    for (int i = tid; i < 32 * F_HID; i += 256) {
        int r = i >> 6, k = i & 63;
        int row = row0 + r;
        xs[i] = (row < N_NODES) ? g_t[row * F_HID + k] : 0.f;
    }
    __syncthreads();
    int rr = tid >> 6;
    int f  = tid & 63;
    float acc[8];
#pragma unroll
    for (int i = 0; i < 8; i++) acc[i] = 0.f;
    for (int k = 0; k < F_HID; k++) {
        float w = Ws[k * F_HID + f];
#pragma unroll
        for (int i = 0; i < 8; i++) acc[i] += xs[(rr + 4 * i) * F_HID + k] * w;
    }
#pragma unroll
    for (int i = 0; i < 8; i++) {
        int row = row0 + rr + 4 * i;
        if (row < N_NODES) g_h[row * F_HID + f] = acc[i];
    }
}

// ---------------- zero the aggregation buffer ----------------
__global__ void zero_agg_kernel() {
    int i = blockIdx.x * blockDim.x + threadIdx.x;
    if (i < N_NODES * F_HID) g_agg[i] = 0.f;
}

// ---------------- edge scatter: g_agg[dst] += g_h[src]  (16 thr/edge, v4 red) ----------------
__global__ void __launch_bounds__(256) scatter_kernel(const int* __restrict__ src,
                                                      const int* __restrict__ dst) {
    long long tid = (long long)blockIdx.x * blockDim.x + threadIdx.x;
    int e  = (int)(tid >> 4);
    int f4 = ((int)tid & 15) * 4;
    if (e >= N_EDGES) return;
    int s = __ldg(&src[e]);
    int d = __ldg(&dst[e]);
    const float4 v = *reinterpret_cast<const float4*>(&g_h[s * F_HID + f4]);
    float* p = &g_agg[d * F_HID + f4];
    asm volatile("red.global.add.v4.f32 [%0], {%1, %2, %3, %4};"
                 :: "l"(p), "f"(v.x), "f"(v.y), "f"(v.z), "f"(v.w) : "memory");
}

// ---------------- finalize layer 1: g_t = relu(agg*norm_in + b1) * norm_out ----------------
// (norm_out pre-fold for layer-2 transform; norm_out > 0 so relu commutes with it)
__global__ void finalize1_kernel(const float* __restrict__ b1) {
    int i = blockIdx.x * blockDim.x + threadIdx.x;
    if (i >= N_NODES * F_HID) return;
    int row = i >> 6, f = i & 63;
    float v = g_agg[i] * g_norm_in[row] + b1[f];
    v = fmaxf(v, 0.f);
    g_t[i] = v * g_norm_out[row];
}

// ---------------- finalize layer 2: out = agg*norm_in + b2 ----------------
__global__ void finalize2_kernel(const float* __restrict__ b2, float* __restrict__ out) {
    int i = blockIdx.x * blockDim.x + threadIdx.x;
    if (i >= N_NODES * F_HID) return;
    int row = i >> 6, f = i & 63;
    out[i] = g_agg[i] * g_norm_in[row] + b2[f];
}

extern "C" void kernel_launch(void* const* d_in, const int* in_sizes, int n_in,
                              void* d_out, int out_size) {
    const float* x   = (const float*)d_in[0];
    const int*   src = (const int*)  d_in[1];
    const int*   dst = (const int*)  d_in[2];
    const float* W1  = (const float*)d_in[3];
    const float* b1  = (const float*)d_in[4];
    const float* W2  = (const float*)d_in[5];
    const float* b2  = (const float*)d_in[6];
    float* out = (float*)d_out;

    const int T = 256;
    const int nodeBlocks = (N_NODES + T - 1) / T;                    // 196
    const int edgeBlocks = (N_EDGES + T - 1) / T;                    // 3125
    const int featBlocks = (N_NODES * F_HID + T - 1) / T;            // 12500
    const int gemmBlocks = (N_NODES + 31) / 32;                      // 1563
    const int scatBlocks = (int)(((long long)N_EDGES * 16 + T - 1) / T);  // 50000

    // degrees + norms
    zero_deg_kernel<<<nodeBlocks, T>>>();
    count_deg_kernel<<<edgeBlocks, T>>>(src, dst);
    norm_kernel<<<nodeBlocks, T>>>();

    // layer 1
    gemm1_kernel<<<gemmBlocks, T>>>(x, W1);
    zero_agg_kernel<<<featBlocks, T>>>();
    scatter_kernel<<<scatBlocks, T>>>(src, dst);
    finalize1_kernel<<<featBlocks, T>>>(b1);

    // layer 2
    gemm2_kernel<<<gemmBlocks, T>>>(W2);
    zero_agg_kernel<<<featBlocks, T>>>();
    scatter_kernel<<<scatBlocks, T>>>(src, dst);
    finalize2_kernel<<<featBlocks, T>>>(b2, out);
}

// round 2
// speedup vs baseline: 1.3905x; 1.3905x over previous
#include <cuda_runtime.h>

#define N_NODES 50000
#define N_EDGES 800000
#define F_IN    128
#define F_HID   64

// ---------------- scratch (no allocations allowed) ----------------
__device__ int   g_deg_out_i[N_NODES];
__device__ int   g_deg_in_i [N_NODES];
__device__ float g_norm_out[N_NODES];
__device__ float g_norm_in [N_NODES];
__device__ int   g_off    [N_NODES + 1];
__device__ int   g_cursor [N_NODES];
__device__ int   g_csr_src[N_EDGES];
__device__ __align__(16) float g_h[N_NODES * F_HID];   // gemm output
__device__ __align__(16) float g_t[N_NODES * F_HID];   // post-layer1 activations (pre-scaled)

// ---------------- degree ----------------
__global__ void zero_deg_kernel() {
    int i = blockIdx.x * blockDim.x + threadIdx.x;
    if (i < N_NODES) { g_deg_out_i[i] = 0; g_deg_in_i[i] = 0; }
}

__global__ void count_deg_kernel(const int* __restrict__ src, const int* __restrict__ dst) {
    int e = blockIdx.x * blockDim.x + threadIdx.x;
    if (e < N_EDGES) {
        atomicAdd(&g_deg_out_i[src[e]], 1);
        atomicAdd(&g_deg_in_i [dst[e]], 1);
    }
}

__global__ void norm_kernel() {
    int i = blockIdx.x * blockDim.x + threadIdx.x;
    if (i < N_NODES) {
        g_norm_out[i] = rsqrtf(fmaxf((float)g_deg_out_i[i], 1.f));
        g_norm_in [i] = rsqrtf(fmaxf((float)g_deg_in_i [i], 1.f));
    }
}

// ---------------- exclusive scan of deg_in -> g_off, g_cursor (single block) ----------------
__global__ void __launch_bounds__(1024) scan_kernel() {
    __shared__ int warp_sums[32];
    __shared__ int base_s;
    int tid = threadIdx.x;
    int lane = tid & 31, wid = tid >> 5;
    if (tid == 0) base_s = 0;
    __syncthreads();
    for (int start = 0; start < N_NODES; start += 1024) {
        int i = start + tid;
        int v = (i < N_NODES) ? g_deg_in_i[i] : 0;
        int x = v;
#pragma unroll
        for (int o = 1; o < 32; o <<= 1) {
            int y = __shfl_up_sync(0xffffffffu, x, o);
            if (lane >= o) x += y;
        }
        if (lane == 31) warp_sums[wid] = x;
        __syncthreads();
        if (wid == 0) {
            int s = warp_sums[lane];
#pragma unroll
            for (int o = 1; o < 32; o <<= 1) {
                int y = __shfl_up_sync(0xffffffffu, s, o);
                if (lane >= o) s += y;
            }
            warp_sums[lane] = s;
        }
        __syncthreads();
        int excl = base_s + (wid ? warp_sums[wid - 1] : 0) + x - v;
        if (i < N_NODES) { g_off[i] = excl; g_cursor[i] = excl; }
        __syncthreads();
        if (tid == 0) base_s += warp_sums[31];
        __syncthreads();
    }
    if (tid == 0) g_off[N_NODES] = N_EDGES;
}

// ---------------- CSR fill: csr_src grouped by dst ----------------
__global__ void fill_kernel(const int* __restrict__ src, const int* __restrict__ dst) {
    int e = blockIdx.x * blockDim.x + threadIdx.x;
    if (e < N_EDGES) {
        int pos = atomicAdd(&g_cursor[dst[e]], 1);
        g_csr_src[pos] = src[e];
    }
}

// ---------------- GEMM1: g_h = (x * norm_out) @ W1  (K=128, N=64) ----------------
// 64 rows/block, 256 threads, 4 rows x 4 feats per thread, LDS.128 for W.
__global__ void __launch_bounds__(256) gemm1_kernel(const float* __restrict__ x,
                                                    const float* __restrict__ W) {
    __shared__ float Ws[F_IN * F_HID];    // 32 KB
    __shared__ float xs[64 * 129];        // 33 KB, pad->conflict-free
    int tid = threadIdx.x;
    for (int i = tid; i < F_IN * F_HID / 4; i += 256)
        ((float4*)Ws)[i] = ((const float4*)W)[i];
    int row0 = blockIdx.x * 64;
    for (int i = tid; i < 64 * 32; i += 256) {
        int r = i >> 5, kq = i & 31;
        int row = row0 + r;
        float4 v = make_float4(0.f, 0.f, 0.f, 0.f);
        float s = 0.f;
        if (row < N_NODES) {
            v = ((const float4*)x)[row * 32 + kq];
            s = g_norm_out[row];
        }
        float* p = &xs[r * 129 + kq * 4];
        p[0] = v.x * s; p[1] = v.y * s; p[2] = v.z * s; p[3] = v.w * s;
    }
    __syncthreads();
    int rg = tid >> 4;       // 0..15, rows rg + 16j
    int fg = tid & 15;       // feature quad
    float4 acc[4];
#pragma unroll
    for (int j = 0; j < 4; j++) acc[j] = make_float4(0.f, 0.f, 0.f, 0.f);
    const float4* Ws4 = (const float4*)Ws;
#pragma unroll 4
    for (int k = 0; k < F_IN; k++) {
        float4 w = Ws4[k * 16 + fg];
#pragma unroll
        for (int j = 0; j < 4; j++) {
            float a = xs[(rg + 16 * j) * 129 + k];
            acc[j].x += a * w.x; acc[j].y += a * w.y;
            acc[j].z += a * w.z; acc[j].w += a * w.w;
        }
    }
#pragma unroll
    for (int j = 0; j < 4; j++) {
        int row = row0 + rg + 16 * j;
        if (row < N_NODES) ((float4*)g_h)[row * 16 + fg] = acc[j];
    }
}

// ---------------- GEMM2: g_h = g_t @ W2  (K=64, N=64) ----------------
__global__ void __launch_bounds__(256) gemm2_kernel(const float* __restrict__ W) {
    __shared__ float Ws[F_HID * F_HID];   // 16 KB
    __shared__ float xs[64 * 65];         // 16.6 KB
    int tid = threadIdx.x;
    for (int i = tid; i < F_HID * F_HID / 4; i += 256)
        ((float4*)Ws)[i] = ((const float4*)W)[i];
    int row0 = blockIdx.x * 64;
    for (int i = tid; i < 64 * 16; i += 256) {
        int r = i >> 4, kq = i & 15;
        int row = row0 + r;
        float4 v = make_float4(0.f, 0.f, 0.f, 0.f);
        if (row < N_NODES) v = ((const float4*)g_t)[row * 16 + kq];
        float* p = &xs[r * 65 + kq * 4];
        p[0] = v.x; p[1] = v.y; p[2] = v.z; p[3] = v.w;
    }
    __syncthreads();
    int rg = tid >> 4;
    int fg = tid & 15;
    float4 acc[4];
#pragma unroll
    for (int j = 0; j < 4; j++) acc[j] = make_float4(0.f, 0.f, 0.f, 0.f);
    const float4* Ws4 = (const float4*)Ws;
#pragma unroll 4
    for (int k = 0; k < F_HID; k++) {
        float4 w = Ws4[k * 16 + fg];
#pragma unroll
        for (int j = 0; j < 4; j++) {
            float a = xs[(rg + 16 * j) * 65 + k];
            acc[j].x += a * w.x; acc[j].y += a * w.y;
            acc[j].z += a * w.z; acc[j].w += a * w.w;
        }
    }
#pragma unroll
    for (int j = 0; j < 4; j++) {
        int row = row0 + rg + 16 * j;
        if (row < N_NODES) ((float4*)g_h)[row * 16 + fg] = acc[j];
    }
}

// ---------------- gather layer 1: g_t = relu(sum(h[src])*norm_in + b1) * norm_out ----------------
// one warp per node, float2 per lane, 2-edge unroll for MLP
__global__ void __launch_bounds__(256) gather1_kernel(const float* __restrict__ b1) {
    int node = blockIdx.x * 8 + (threadIdx.x >> 5);
    int lane = threadIdx.x & 31;
    if (node >= N_NODES) return;
    int beg = g_off[node], end = g_off[node + 1];
    const float2* h2 = (const float2*)g_h;
    float ax = 0.f, ay = 0.f, bx = 0.f, by = 0.f;
    int j = beg;
    for (; j + 1 < end; j += 2) {
        int s0 = __ldg(&g_csr_src[j]);
        int s1 = __ldg(&g_csr_src[j + 1]);
        float2 v0 = h2[s0 * 32 + lane];
        float2 v1 = h2[s1 * 32 + lane];
        ax += v0.x; ay += v0.y;
        bx += v1.x; by += v1.y;
    }
    if (j < end) {
        int s = __ldg(&g_csr_src[j]);
        float2 v = h2[s * 32 + lane];
        ax += v.x; ay += v.y;
    }
    ax += bx; ay += by;
    float ni = g_norm_in[node], no = g_norm_out[node];
    float2 bb = ((const float2*)b1)[lane];
    float2 o;
    o.x = fmaxf(ax * ni + bb.x, 0.f) * no;
    o.y = fmaxf(ay * ni + bb.y, 0.f) * no;
    ((float2*)g_t)[node * 32 + lane] = o;
}

// ---------------- gather layer 2: out = sum(h[src])*norm_in + b2 ----------------
__global__ void __launch_bounds__(256) gather2_kernel(const float* __restrict__ b2,
                                                      float* __restrict__ out) {
    int node = blockIdx.x * 8 + (threadIdx.x >> 5);
    int lane = threadIdx.x & 31;
    if (node >= N_NODES) return;
    int beg = g_off[node], end = g_off[node + 1];
    const float2* h2 = (const float2*)g_h;
    float ax = 0.f, ay = 0.f, bx = 0.f, by = 0.f;
    int j = beg;
    for (; j + 1 < end; j += 2) {
        int s0 = __ldg(&g_csr_src[j]);
        int s1 = __ldg(&g_csr_src[j + 1]);
        float2 v0 = h2[s0 * 32 + lane];
        float2 v1 = h2[s1 * 32 + lane];
        ax += v0.x; ay += v0.y;
        bx += v1.x; by += v1.y;
    }
    if (j < end) {
        int s = __ldg(&g_csr_src[j]);
        float2 v = h2[s * 32 + lane];
        ax += v.x; ay += v.y;
    }
    ax += bx; ay += by;
    float ni = g_norm_in[node];
    float2 bb = ((const float2*)b2)[lane];
    float2 o;
    o.x = ax * ni + bb.x;
    o.y = ay * ni + bb.y;
    ((float2*)out)[node * 32 + lane] = o;
}

extern "C" void kernel_launch(void* const* d_in, const int* in_sizes, int n_in,
                              void* d_out, int out_size) {
    const float* x   = (const float*)d_in[0];
    const int*   src = (const int*)  d_in[1];
    const int*   dst = (const int*)  d_in[2];
    const float* W1  = (const float*)d_in[3];
    const float* b1  = (const float*)d_in[4];
    const float* W2  = (const float*)d_in[5];
    const float* b2  = (const float*)d_in[6];
    float* out = (float*)d_out;

    const int T = 256;
    const int nodeBlocks  = (N_NODES + T - 1) / T;   // 196
    const int edgeBlocks  = (N_EDGES + T - 1) / T;   // 3125
    const int gemmBlocks  = (N_NODES + 63) / 64;     // 782
    const int gatherBlocks = (N_NODES + 7) / 8;      // 6250

    // degrees, norms, CSR
    zero_deg_kernel<<<nodeBlocks, T>>>();
    count_deg_kernel<<<edgeBlocks, T>>>(src, dst);
    norm_kernel<<<nodeBlocks, T>>>();
    scan_kernel<<<1, 1024>>>();
    fill_kernel<<<edgeBlocks, T>>>(src, dst);

    // layer 1
    gemm1_kernel<<<gemmBlocks, T>>>(x, W1);
    gather1_kernel<<<gatherBlocks, T>>>(b1);

    // layer 2
    gemm2_kernel<<<gemmBlocks, T>>>(W2);
    gather2_kernel<<<gatherBlocks, T>>>(b2, out);
}

// round 3
// speedup vs baseline: 1.7336x; 1.2467x over previous
#include <cuda_runtime.h>

#define N_NODES 50000
#define N_EDGES 800000
#define F_IN    128
#define F_HID   64
#define SCAN_B  1024
#define SCAN_NB ((N_NODES + SCAN_B - 1) / SCAN_B)   // 49

// ---------------- scratch (no allocations allowed) ----------------
__device__ int   g_deg_out_i[N_NODES];
__device__ int   g_deg_in_i [N_NODES];
__device__ float g_norm_out[N_NODES];
__device__ float g_norm_in [N_NODES];
__device__ int   g_off    [N_NODES + 1];
__device__ int   g_cursor [N_NODES];
__device__ int   g_bsum   [64];
__device__ int   g_bpre   [64];
__device__ int   g_csr_src[N_EDGES];
__device__ __align__(16) float g_h[N_NODES * F_HID];   // gemm output
__device__ __align__(16) float g_t[N_NODES * F_HID];   // post-layer1 activations (pre-scaled)

// ---------------- degree ----------------
__global__ void zero_deg_kernel() {
    int i = blockIdx.x * blockDim.x + threadIdx.x;
    if (i < N_NODES) { g_deg_out_i[i] = 0; g_deg_in_i[i] = 0; }
}

__global__ void count_deg_kernel(const int* __restrict__ src, const int* __restrict__ dst) {
    int e = blockIdx.x * blockDim.x + threadIdx.x;
    if (e < N_EDGES) {
        atomicAdd(&g_deg_out_i[src[e]], 1);
        atomicAdd(&g_deg_in_i [dst[e]], 1);
    }
}

// ---------------- scan phase A: per-block exclusive scan + block sums ----------------
__global__ void __launch_bounds__(SCAN_B) scanA_kernel() {
    __shared__ int warp_sums[32];
    int tid = threadIdx.x;
    int lane = tid & 31, wid = tid >> 5;
    int i = blockIdx.x * SCAN_B + tid;
    int v = (i < N_NODES) ? g_deg_in_i[i] : 0;
    int x = v;
#pragma unroll
    for (int o = 1; o < 32; o <<= 1) {
        int y = __shfl_up_sync(0xffffffffu, x, o);
        if (lane >= o) x += y;
    }
    if (lane == 31) warp_sums[wid] = x;
    __syncthreads();
    if (wid == 0) {
        int s = warp_sums[lane];
#pragma unroll
        for (int o = 1; o < 32; o <<= 1) {
            int y = __shfl_up_sync(0xffffffffu, s, o);
            if (lane >= o) s += y;
        }
        warp_sums[lane] = s;
    }
    __syncthreads();
    int excl = (wid ? warp_sums[wid - 1] : 0) + x - v;
    if (i < N_NODES) g_off[i] = excl;
    if (tid == SCAN_B - 1) g_bsum[blockIdx.x] = excl + v;
}

// ---------------- scan phase B: scan the block sums (1 block, 64 threads) ----------------
__global__ void scanB_kernel() {
    __shared__ int w0_total;
    int tid = threadIdx.x;
    int lane = tid & 31, wid = tid >> 5;
    int v = (tid < SCAN_NB) ? g_bsum[tid] : 0;
    int x = v;
#pragma unroll
    for (int o = 1; o < 32; o <<= 1) {
        int y = __shfl_up_sync(0xffffffffu, x, o);
        if (lane >= o) x += y;
    }
    if (wid == 0 && lane == 31) w0_total = x;
    __syncthreads();
    int excl = x - v + (wid ? w0_total : 0);
    if (tid < SCAN_NB) g_bpre[tid] = excl;
}

// ---------------- scan phase C: finalize offsets + cursors + norms ----------------
__global__ void __launch_bounds__(SCAN_B) scanC_kernel() {
    int i = blockIdx.x * SCAN_B + threadIdx.x;
    if (i < N_NODES) {
        int off = g_off[i] + g_bpre[blockIdx.x];
        g_off[i] = off;
        g_cursor[i] = off;
        g_norm_out[i] = rsqrtf(fmaxf((float)g_deg_out_i[i], 1.f));
        g_norm_in [i] = rsqrtf(fmaxf((float)g_deg_in_i [i], 1.f));
    }
    if (i == 0) g_off[N_NODES] = N_EDGES;
}

// ---------------- CSR fill: csr_src grouped by dst ----------------
__global__ void fill_kernel(const int* __restrict__ src, const int* __restrict__ dst) {
    int e = blockIdx.x * blockDim.x + threadIdx.x;
    if (e < N_EDGES) {
        int pos = atomicAdd(&g_cursor[dst[e]], 1);
        g_csr_src[pos] = src[e];
    }
}

// ---------------- GEMM1: g_h = (x * norm_out) @ W1  (K=128, N=64) ----------------
__global__ void __launch_bounds__(256) gemm1_kernel(const float* __restrict__ x,
                                                    const float* __restrict__ W) {
    __shared__ float Ws[F_IN * F_HID];    // 32 KB
    __shared__ float xs[64 * 129];        // 33 KB, pad->conflict-free
    int tid = threadIdx.x;
    for (int i = tid; i < F_IN * F_HID / 4; i += 256)
        ((float4*)Ws)[i] = ((const float4*)W)[i];
    int row0 = blockIdx.x * 64;
    for (int i = tid; i < 64 * 32; i += 256) {
        int r = i >> 5, kq = i & 31;
        int row = row0 + r;
        float4 v = make_float4(0.f, 0.f, 0.f, 0.f);
        float s = 0.f;
        if (row < N_NODES) {
            v = ((const float4*)x)[row * 32 + kq];
            s = g_norm_out[row];
        }
        float* p = &xs[r * 129 + kq * 4];
        p[0] = v.x * s; p[1] = v.y * s; p[2] = v.z * s; p[3] = v.w * s;
    }
    __syncthreads();
    int rg = tid >> 4;       // 0..15, rows rg + 16j
    int fg = tid & 15;       // feature quad
    float4 acc[4];
#pragma unroll
    for (int j = 0; j < 4; j++) acc[j] = make_float4(0.f, 0.f, 0.f, 0.f);
    const float4* Ws4 = (const float4*)Ws;
#pragma unroll 4
    for (int k = 0; k < F_IN; k++) {
        float4 w = Ws4[k * 16 + fg];
#pragma unroll
        for (int j = 0; j < 4; j++) {
            float a = xs[(rg + 16 * j) * 129 + k];
            acc[j].x += a * w.x; acc[j].y += a * w.y;
            acc[j].z += a * w.z; acc[j].w += a * w.w;
        }
    }
#pragma unroll
    for (int j = 0; j < 4; j++) {
        int row = row0 + rg + 16 * j;
        if (row < N_NODES) ((float4*)g_h)[row * 16 + fg] = acc[j];
    }
}

// ---------------- GEMM2: g_h = g_t @ W2  (K=64, N=64) ----------------
__global__ void __launch_bounds__(256) gemm2_kernel(const float* __restrict__ W) {
    __shared__ float Ws[F_HID * F_HID];   // 16 KB
    __shared__ float xs[64 * 65];         // 16.6 KB
    int tid = threadIdx.x;
    for (int i = tid; i < F_HID * F_HID / 4; i += 256)
        ((float4*)Ws)[i] = ((const float4*)W)[i];
    int row0 = blockIdx.x * 64;
    for (int i = tid; i < 64 * 16; i += 256) {
        int r = i >> 4, kq = i & 15;
        int row = row0 + r;
        float4 v = make_float4(0.f, 0.f, 0.f, 0.f);
        if (row < N_NODES) v = ((const float4*)g_t)[row * 16 + kq];
        float* p = &xs[r * 65 + kq * 4];
        p[0] = v.x; p[1] = v.y; p[2] = v.z; p[3] = v.w;
    }
    __syncthreads();
    int rg = tid >> 4;
    int fg = tid & 15;
    float4 acc[4];
#pragma unroll
    for (int j = 0; j < 4; j++) acc[j] = make_float4(0.f, 0.f, 0.f, 0.f);
    const float4* Ws4 = (const float4*)Ws;
#pragma unroll 4
    for (int k = 0; k < F_HID; k++) {
        float4 w = Ws4[k * 16 + fg];
#pragma unroll
        for (int j = 0; j < 4; j++) {
            float a = xs[(rg + 16 * j) * 65 + k];
            acc[j].x += a * w.x; acc[j].y += a * w.y;
            acc[j].z += a * w.z; acc[j].w += a * w.w;
        }
    }
#pragma unroll
    for (int j = 0; j < 4; j++) {
        int row = row0 + rg + 16 * j;
        if (row < N_NODES) ((float4*)g_h)[row * 16 + fg] = acc[j];
    }
}

// ---------------- gather layer 1: g_t = relu(sum(h[src])*norm_in + b1) * norm_out ----------------
__global__ void __launch_bounds__(256) gather1_kernel(const float* __restrict__ b1) {
    int node = blockIdx.x * 8 + (threadIdx.x >> 5);
    int lane = threadIdx.x & 31;
    if (node >= N_NODES) return;
    int beg = g_off[node], end = g_off[node + 1];
    const float2* h2 = (const float2*)g_h;
    float ax = 0.f, ay = 0.f, bx = 0.f, by = 0.f;
    int j = beg;
    for (; j + 1 < end; j += 2) {
        int s0 = __ldg(&g_csr_src[j]);
        int s1 = __ldg(&g_csr_src[j + 1]);
        float2 v0 = h2[s0 * 32 + lane];
        float2 v1 = h2[s1 * 32 + lane];
        ax += v0.x; ay += v0.y;
        bx += v1.x; by += v1.y;
    }
    if (j < end) {
        int s = __ldg(&g_csr_src[j]);
        float2 v = h2[s * 32 + lane];
        ax += v.x; ay += v.y;
    }
    ax += bx; ay += by;
    float ni = g_norm_in[node], no = g_norm_out[node];
    float2 bb = ((const float2*)b1)[lane];
    float2 o;
    o.x = fmaxf(ax * ni + bb.x, 0.f) * no;
    o.y = fmaxf(ay * ni + bb.y, 0.f) * no;
    ((float2*)g_t)[node * 32 + lane] = o;
}

// ---------------- gather layer 2: out = sum(h[src])*norm_in + b2 ----------------
__global__ void __launch_bounds__(256) gather2_kernel(const float* __restrict__ b2,
                                                      float* __restrict__ out) {
    int node = blockIdx.x * 8 + (threadIdx.x >> 5);
    int lane = threadIdx.x & 31;
    if (node >= N_NODES) return;
    int beg = g_off[node], end = g_off[node + 1];
    const float2* h2 = (const float2*)g_h;
    float ax = 0.f, ay = 0.f, bx = 0.f, by = 0.f;
    int j = beg;
    for (; j + 1 < end; j += 2) {
        int s0 = __ldg(&g_csr_src[j]);
        int s1 = __ldg(&g_csr_src[j + 1]);
        float2 v0 = h2[s0 * 32 + lane];
        float2 v1 = h2[s1 * 32 + lane];
        ax += v0.x; ay += v0.y;
        bx += v1.x; by += v1.y;
    }
    if (j < end) {
        int s = __ldg(&g_csr_src[j]);
        float2 v = h2[s * 32 + lane];
        ax += v.x; ay += v.y;
    }
    ax += bx; ay += by;
    float ni = g_norm_in[node];
    float2 bb = ((const float2*)b2)[lane];
    float2 o;
    o.x = ax * ni + bb.x;
    o.y = ay * ni + bb.y;
    ((float2*)out)[node * 32 + lane] = o;
}

extern "C" void kernel_launch(void* const* d_in, const int* in_sizes, int n_in,
                              void* d_out, int out_size) {
    const float* x   = (const float*)d_in[0];
    const int*   src = (const int*)  d_in[1];
    const int*   dst = (const int*)  d_in[2];
    const float* W1  = (const float*)d_in[3];
    const float* b1  = (const float*)d_in[4];
    const float* W2  = (const float*)d_in[5];
    const float* b2  = (const float*)d_in[6];
    float* out = (float*)d_out;

    const int T = 256;
    const int nodeBlocks   = (N_NODES + T - 1) / T;   // 196
    const int edgeBlocks   = (N_EDGES + T - 1) / T;   // 3125
    const int gemmBlocks   = (N_NODES + 63) / 64;     // 782
    const int gatherBlocks = (N_NODES + 7) / 8;       // 6250

    // degrees, norms, CSR (parallel 3-phase scan)
    zero_deg_kernel<<<nodeBlocks, T>>>();
    count_deg_kernel<<<edgeBlocks, T>>>(src, dst);
    scanA_kernel<<<SCAN_NB, SCAN_B>>>();
    scanB_kernel<<<1, 64>>>();
    scanC_kernel<<<SCAN_NB, SCAN_B>>>();
    fill_kernel<<<edgeBlocks, T>>>(src, dst);

    // layer 1
    gemm1_kernel<<<gemmBlocks, T>>>(x, W1);
    gather1_kernel<<<gatherBlocks, T>>>(b1);

    // layer 2
    gemm2_kernel<<<gemmBlocks, T>>>(W2);
    gather2_kernel<<<gatherBlocks, T>>>(b2, out);
}